// round 5
// baseline (speedup 1.0000x reference)
#include <cuda_runtime.h>
#include <math.h>

// Problem shape (fixed by dataset): x[2,2048,2048], gate_w[2048,8], gate_b[8],
// W1[8,2048,5632], b1[8,5632], W2[8,5632,2048], b2[8,2048], out fp32 [2,2048,2048].
#define T_TOK 4096
#define D_DIM 2048
#define F_DIM 5632
#define E_NUM 8
#define N_ASSIGN (T_TOK * 2)
#define MAX_TILES 96   // sum over experts of ceil(count/128) <= 64 + 8 = 72

// ---------------- static device scratch (no allocations allowed) ----------------
__device__ int   g_cnt[E_NUM];
__device__ int   g_cur[E_NUM];
__device__ int   g_tok_e[T_TOK][2];
__device__ float g_tok_w[T_TOK][2];
__device__ int   g_tok_pos[T_TOK][2];
__device__ int   g_assign_tok[N_ASSIGN];
__device__ float g_assign_w[N_ASSIGN];
__device__ int   g_ntiles;
__device__ int   g_tile_e[MAX_TILES];
__device__ int   g_tile_r0[MAX_TILES];
__device__ int   g_tile_nr[MAX_TILES];
__device__ float g_h[(size_t)N_ASSIGN * F_DIM];   // GELU(x@W1+b1) per assignment (~184MB)
__device__ float g_y[(size_t)N_ASSIGN * D_DIM];   // weighted expert outputs   (~67MB)

// ---------------- f32x2 packed math helpers (sm_100+) ----------------
__device__ __forceinline__ unsigned long long pack2(float lo, float hi) {
    unsigned long long r;
    asm("mov.b64 %0, {%1, %2};" : "=l"(r) : "f"(lo), "f"(hi));
    return r;
}
__device__ __forceinline__ void unpack2(unsigned long long v, float& lo, float& hi) {
    asm("mov.b64 {%0, %1}, %2;" : "=f"(lo), "=f"(hi) : "l"(v));
}
__device__ __forceinline__ void fma2(unsigned long long& d,
                                     unsigned long long a, unsigned long long b) {
    asm("fma.rn.f32x2 %0, %1, %2, %0;" : "+l"(d) : "l"(a), "l"(b));
}

__device__ __forceinline__ float gelu_exact(float v) {
    return 0.5f * v * (1.0f + erff(v * 0.70710678118654752440f));
}

// ---------------- kernel 0: zero per-expert counters ----------------
__global__ void k_init() {
    int i = threadIdx.x;
    if (i < E_NUM) g_cnt[i] = 0;
}

// ---------------- kernel 1: gating (logits -> softmax -> top-2) ----------------
__global__ void k_gate(const float* __restrict__ x,
                       const float* __restrict__ gw,
                       const float* __restrict__ gb) {
    int t = blockIdx.x;
    int tid = threadIdx.x;                 // 128 threads
    const float* xr = x + (size_t)t * D_DIM;

    float part[E_NUM];
#pragma unroll
    for (int e = 0; e < E_NUM; e++) part[e] = 0.0f;

    for (int d = tid; d < D_DIM; d += 128) {
        float xv = xr[d];
        const float4* g4 = (const float4*)(gw + (size_t)d * E_NUM);
        float4 g0 = g4[0];
        float4 g1 = g4[1];
        part[0] = fmaf(xv, g0.x, part[0]);
        part[1] = fmaf(xv, g0.y, part[1]);
        part[2] = fmaf(xv, g0.z, part[2]);
        part[3] = fmaf(xv, g0.w, part[3]);
        part[4] = fmaf(xv, g1.x, part[4]);
        part[5] = fmaf(xv, g1.y, part[5]);
        part[6] = fmaf(xv, g1.z, part[6]);
        part[7] = fmaf(xv, g1.w, part[7]);
    }

    __shared__ float red[E_NUM][128];
#pragma unroll
    for (int e = 0; e < E_NUM; e++) red[e][tid] = part[e];
    __syncthreads();
    for (int s = 64; s > 0; s >>= 1) {
        if (tid < s) {
#pragma unroll
            for (int e = 0; e < E_NUM; e++) red[e][tid] += red[e][tid + s];
        }
        __syncthreads();
    }

    if (tid == 0) {
        float l[E_NUM];
#pragma unroll
        for (int e = 0; e < E_NUM; e++) l[e] = red[e][0] + gb[e];
        // argmax (first occurrence on ties, matching lax.top_k)
        int i0 = 0;
#pragma unroll
        for (int e = 1; e < E_NUM; e++) if (l[e] > l[i0]) i0 = e;
        int i1 = (i0 == 0) ? 1 : 0;
#pragma unroll
        for (int e = 0; e < E_NUM; e++)
            if (e != i0 && l[e] > l[i1]) i1 = e;

        float m = l[i0];
        float s = 0.0f;
#pragma unroll
        for (int e = 0; e < E_NUM; e++) s += expf(l[e] - m);
        float w0 = 1.0f / s;               // exp(0)/s
        float w1 = expf(l[i1] - m) / s;

        g_tok_e[t][0] = i0;  g_tok_e[t][1] = i1;
        g_tok_w[t][0] = w0;  g_tok_w[t][1] = w1;
        atomicAdd(&g_cnt[i0], 1);
        atomicAdd(&g_cnt[i1], 1);
    }
}

// ---------------- kernel 2: scan counts -> offsets + tile list ----------------
__global__ void k_scan() {
    int off[E_NUM + 1];
    off[0] = 0;
    for (int e = 0; e < E_NUM; e++) off[e + 1] = off[e] + g_cnt[e];
    for (int e = 0; e < E_NUM; e++) g_cur[e] = off[e];
    int nt = 0;
    for (int e = 0; e < E_NUM; e++) {
        for (int r = off[e]; r < off[e + 1]; r += 128) {
            g_tile_e[nt]  = e;
            g_tile_r0[nt] = r;
            int rem = off[e + 1] - r;
            g_tile_nr[nt] = rem < 128 ? rem : 128;
            nt++;
        }
    }
    g_ntiles = nt;
}

// ---------------- kernel 3: scatter tokens into per-expert segments ----------------
__global__ void k_scatter() {
    int t = blockIdx.x * blockDim.x + threadIdx.x;
    if (t >= T_TOK) return;
#pragma unroll
    for (int k = 0; k < 2; k++) {
        int e = g_tok_e[t][k];
        int pos = atomicAdd(&g_cur[e], 1);
        g_assign_tok[pos] = t;
        g_assign_w[pos]   = g_tok_w[t][k];
        g_tok_pos[t][k]   = pos;
    }
}

// ---------------- grouped GEMM (MODE 0: x@W1 + GELU -> g_h; MODE 1: g_h@W2 *w -> g_y)
// 128x128 tile, BK=8, 256 threads, 8x8 micro-tile per thread, fma.rn.f32x2 inner,
// software-pipelined global->smem staging (prefetch next k-tile into registers).
template <int MODE>
__global__ __launch_bounds__(256, 2) void moe_gemm(const float* __restrict__ Xin,
                                                   const float* __restrict__ Wexp,
                                                   const float* __restrict__ bias) {
    constexpr int K = (MODE == 0) ? D_DIM : F_DIM;
    constexpr int N = (MODE == 0) ? F_DIM : D_DIM;

    int tile = blockIdx.x;
    if (tile >= g_ntiles) return;
    int e     = g_tile_e[tile];
    int row0  = g_tile_r0[tile];
    int nrows = g_tile_nr[tile];
    int n0    = blockIdx.y * 128;

    const float* Bp = Wexp + (size_t)e * K * N;

    __shared__ unsigned long long As2[8][128];   // A values duplicated into both f32x2 lanes
    __shared__ float              Bs[8][128];

    int tid    = threadIdx.x;
    int arow_l = tid >> 1;                 // 0..127 : A tile row this thread loads
    int kseg   = (tid & 1) * 4;            // k sub-offset 0 or 4
    int rowc   = arow_l < nrows ? arow_l : (nrows - 1);   // clamp padded rows

    const float* Aptr;
    if (MODE == 0) {
        int token = g_assign_tok[row0 + rowc];
        Aptr = Xin + (size_t)token * D_DIM + kseg;
    } else {
        Aptr = g_h + (size_t)(row0 + rowc) * F_DIM + kseg;
    }
    int bkr = tid >> 5;                    // 0..7 : B tile k-row
    int bc  = (tid & 31) * 4;              // B tile col offset
    const float* Bptr = Bp + (size_t)bkr * N + n0 + bc;

    int ty = tid >> 4, tx = tid & 15;
    int rowb = ty * 8, colb = tx * 8;

    unsigned long long acc[8][4];
#pragma unroll
    for (int r = 0; r < 8; r++)
#pragma unroll
        for (int j = 0; j < 4; j++) acc[r][j] = 0ull;

    // ---- prologue: load first k-tile ----
    float4 av4 = *(const float4*)(Aptr);
    float4 bv4 = *(const float4*)(Bptr);

    constexpr int KT = K / 8;
    for (int kt = 0; kt < KT; kt++) {
        As2[kseg + 0][arow_l] = pack2(av4.x, av4.x);
        As2[kseg + 1][arow_l] = pack2(av4.y, av4.y);
        As2[kseg + 2][arow_l] = pack2(av4.z, av4.z);
        As2[kseg + 3][arow_l] = pack2(av4.w, av4.w);
        *(float4*)&Bs[bkr][bc] = bv4;
        __syncthreads();

        // ---- prefetch next k-tile while computing this one ----
        if (kt + 1 < KT) {
            Aptr += 8;
            Bptr += (size_t)8 * N;
            av4 = *(const float4*)(Aptr);
            bv4 = *(const float4*)(Bptr);
        }

#pragma unroll
        for (int kk = 0; kk < 8; kk++) {
            ulonglong2 a01 = *(const ulonglong2*)&As2[kk][rowb + 0];
            ulonglong2 a23 = *(const ulonglong2*)&As2[kk][rowb + 2];
            ulonglong2 a45 = *(const ulonglong2*)&As2[kk][rowb + 4];
            ulonglong2 a67 = *(const ulonglong2*)&As2[kk][rowb + 6];
            ulonglong2 b01 = *(const ulonglong2*)&Bs[kk][colb + 0];
            ulonglong2 b23 = *(const ulonglong2*)&Bs[kk][colb + 4];
            unsigned long long av[8] = {a01.x, a01.y, a23.x, a23.y,
                                        a45.x, a45.y, a67.x, a67.y};
            unsigned long long bv[4] = {b01.x, b01.y, b23.x, b23.y};
#pragma unroll
            for (int r = 0; r < 8; r++)
#pragma unroll
                for (int j = 0; j < 4; j++) fma2(acc[r][j], av[r], bv[j]);
        }
        __syncthreads();
    }

    // ---- epilogue ----
    const float* brow = bias + (size_t)e * N + n0 + colb;
    float bl[8];
#pragma unroll
    for (int j = 0; j < 8; j++) bl[j] = brow[j];

#pragma unroll
    for (int r = 0; r < 8; r++) {
        int lr = rowb + r;
        if (lr >= nrows) continue;
        int arow = row0 + lr;
        float wrow = (MODE == 1) ? g_assign_w[arow] : 0.0f;
#pragma unroll
        for (int j = 0; j < 4; j++) {
            float lo, hi;
            unpack2(acc[r][j], lo, hi);
            int c0 = n0 + colb + 2 * j;
            if (MODE == 0) {
                float v0 = lo + bl[2 * j];
                float v1 = hi + bl[2 * j + 1];
                g_h[(size_t)arow * F_DIM + c0]     = gelu_exact(v0);
                g_h[(size_t)arow * F_DIM + c0 + 1] = gelu_exact(v1);
            } else {
                float v0 = (lo + bl[2 * j]) * wrow;
                float v1 = (hi + bl[2 * j + 1]) * wrow;
                g_y[(size_t)arow * D_DIM + c0]     = v0;
                g_y[(size_t)arow * D_DIM + c0 + 1] = v1;
            }
        }
    }
}

// ---------------- kernel 6: combine the two expert contributions per token ----------------
__global__ void k_combine(float* __restrict__ out) {
    const int nj = D_DIM / 4;
    int idx = blockIdx.x * blockDim.x + threadIdx.x;
    if (idx >= T_TOK * nj) return;
    int t = idx / nj;
    int j = idx - t * nj;
    int p0 = g_tok_pos[t][0];
    int p1 = g_tok_pos[t][1];
    const float4* y4 = (const float4*)g_y;
    float4 a = y4[(size_t)p0 * nj + j];
    float4 b = y4[(size_t)p1 * nj + j];
    float4 o;
    o.x = a.x + b.x;
    o.y = a.y + b.y;
    o.z = a.z + b.z;
    o.w = a.w + b.w;
    ((float4*)out)[idx] = o;
}

// ---------------- launch ----------------
extern "C" void kernel_launch(void* const* d_in, const int* in_sizes, int n_in,
                              void* d_out, int out_size) {
    const float* x   = (const float*)d_in[0];
    const float* gw  = (const float*)d_in[1];
    const float* gb  = (const float*)d_in[2];
    const float* W1  = (const float*)d_in[3];
    const float* b1  = (const float*)d_in[4];
    const float* W2  = (const float*)d_in[5];
    const float* b2  = (const float*)d_in[6];
    float* out = (float*)d_out;

    k_init<<<1, 32>>>();
    k_gate<<<T_TOK, 128>>>(x, gw, gb);
    k_scan<<<1, 1>>>();
    k_scatter<<<(T_TOK + 255) / 256, 256>>>();

    // max m-tiles = 4096*2/128 + (E-1) partials <= 72
    moe_gemm<0><<<dim3(72, F_DIM / 128), 256>>>(x, W1, b1);
    moe_gemm<1><<<dim3(72, D_DIM / 128), 256>>>(x, W2, b2);

    k_combine<<<(T_TOK * (D_DIM / 4) + 255) / 256, 256>>>(out);
}